// round 14
// baseline (speedup 1.0000x reference)
#include <cuda_runtime.h>
#include <cuda_fp16.h>
#include <cstdint>
#include <math.h>

// ---------------- problem dims ----------------
#define BB    2
#define SS    2048
#define HID   2048
#define VDIM  4096
#define KEYD  2048
#define NVH   32
#define ROWS  4096            // B*S
#define PD2   12416           // 12288 qkvz + 64 ba + 64 pad

// ---------------- static scratch ----------------
__device__ float  g_qkvz2[(size_t)ROWS * PD2];     // fp32 qkvz+ba fused output
__device__ float  g_qn  [(size_t)ROWS * KEYD];
__device__ float  g_kn  [(size_t)ROWS * KEYD];
__device__ float  g_v   [(size_t)ROWS * VDIM];
__device__ float  g_beta[ROWS * NVH];
__device__ float  g_gl  [ROWS * NVH];              // log-decay g (NOT exp)
__device__ float  g_core[(size_t)ROWS * VDIM];
__device__ __half g_xh  [(size_t)ROWS * HID];
__device__ __half g_wh1 [(size_t)PD2 * HID];
__device__ __half g_gh  [(size_t)ROWS * VDIM];
__device__ __half g_woh [(size_t)HID * VDIM];

// ---------------- helpers ----------------
__device__ __forceinline__ uint32_t smem_u32(const void* p) {
    uint32_t a;
    asm("{ .reg .u64 t; cvta.to.shared.u64 t, %1; cvt.u32.u64 %0, t; }" : "=r"(a) : "l"(p));
    return a;
}
#define SW128(o) ((o) ^ (((o) >> 3) & 0x70))

__device__ __forceinline__ void mma_f16(float* c, unsigned a0, unsigned a1,
                                        unsigned a2, unsigned a3, unsigned b0, unsigned b1) {
    asm volatile(
        "mma.sync.aligned.m16n8k16.row.col.f32.f16.f16.f32 "
        "{%0,%1,%2,%3}, {%4,%5,%6,%7}, {%8,%9}, {%0,%1,%2,%3};"
        : "+f"(c[0]), "+f"(c[1]), "+f"(c[2]), "+f"(c[3])
        : "r"(a0), "r"(a1), "r"(a2), "r"(a3), "r"(b0), "r"(b1));
}

// Warp-level small GEMM: out 16 x (NT*8) block at (r0, c0).
// A[row][k] (row-major, lda), B[col][k] (row-major, ldb) -> C = A * B^T.
template<int NT, int KS>
__device__ __forceinline__ void wgemm(const __half* A, int lda, const __half* B, int ldb,
                                      int r0, int c0, int lane, float acc[NT][4])
{
    const int g  = lane >> 2;
    const int q2 = (lane & 3) * 2;
#pragma unroll
    for (int ks = 0; ks < KS; ks++) {
        const int k0 = ks * 16;
        const __half* ap = A + (r0 + g) * lda + k0 + q2;
        unsigned a0 = *(const unsigned*)ap;
        unsigned a1 = *(const unsigned*)(ap + 8 * lda);
        unsigned a2 = *(const unsigned*)(ap + 8);
        unsigned a3 = *(const unsigned*)(ap + 8 * lda + 8);
        const __half* bp = B + (c0 + g) * ldb + k0 + q2;
#pragma unroll
        for (int n = 0; n < NT; n++) {
            unsigned b0 = *(const unsigned*)(bp + n * 8 * ldb);
            unsigned b1 = *(const unsigned*)(bp + n * 8 * ldb + 8);
            mma_f16(acc[n], a0, a1, a2, a3, b0, b1);
        }
    }
}

// =====================================================================
// fp16 tensor-core GEMM: C[M,N] = A[M,K] * B[N,K]^T
// =====================================================================
#define BKH   64
#define STG_B 32768
#define GSMEM (3 * STG_B)

template <typename OutT>
__global__ __launch_bounds__(256, 2) void gemm_f16(
    const __half* __restrict__ A, const __half* __restrict__ B,
    OutT* __restrict__ C, int M, int N, int K)
{
    extern __shared__ char sm[];
    const int tid  = threadIdx.x;
    const int warp = tid >> 5, lane = tid & 31;
    const int bm   = blockIdx.y * 128;
    const int bn   = blockIdx.x * 128;
    const int wm   = (warp & 1) * 64;
    const int wn   = (warp >> 1) * 32;

    auto loadStage = [&](int st, int kt) {
        char* as = sm + st * STG_B;
        char* bs = as + 16384;
#pragma unroll
        for (int j = 0; j < 4; j++) {
            const int idx = tid + j * 256;
            const int row = idx >> 3;
            const int c   = idx & 7;
            const uint32_t so = SW128((uint32_t)(row * 128 + c * 16));
            uint32_t da = smem_u32(as + so);
            const __half* sa = A + (size_t)(bm + row) * K + kt + c * 8;
            asm volatile("cp.async.cg.shared.global [%0], [%1], 16;" :: "r"(da), "l"(sa));
            uint32_t db = smem_u32(bs + so);
            const __half* sb = B + (size_t)(bn + row) * K + kt + c * 8;
            asm volatile("cp.async.cg.shared.global [%0], [%1], 16;" :: "r"(db), "l"(sb));
        }
        asm volatile("cp.async.commit_group;");
    };

    float acc[4][4][4];
#pragma unroll
    for (int i = 0; i < 4; i++)
#pragma unroll
        for (int j = 0; j < 4; j++)
#pragma unroll
            for (int r = 0; r < 4; r++) acc[i][j][r] = 0.f;

    const int S = K / BKH;
    loadStage(0, 0);
    loadStage(1, BKH);

    const int aRowOff = (lane & 7) + ((lane >> 3) & 1) * 8;
    const int aKOff   = (lane >> 4) * 16;
    const int bRow2   = (lane & 7) + ((lane >> 4) * 8);
    const int bK2     = ((lane >> 3) & 1) * 16;

    for (int s = 0; s < S; s++) {
        if (s + 1 < S) asm volatile("cp.async.wait_group 1;" ::: "memory");
        else           asm volatile("cp.async.wait_group 0;" ::: "memory");
        __syncthreads();
        if (s + 2 < S) loadStage((s + 2) % 3, (s + 2) * BKH);

        const uint32_t aBase = smem_u32(sm + (s % 3) * STG_B);
        const uint32_t bBase = aBase + 16384;

#pragma unroll
        for (int kb = 0; kb < 4; kb++) {
            uint32_t af[4][4], bf[2][4];
#pragma unroll
            for (int i = 0; i < 4; i++) {
                const uint32_t ad = aBase +
                    SW128((uint32_t)((wm + i * 16 + aRowOff) * 128 + kb * 32 + aKOff));
                asm volatile("ldmatrix.sync.aligned.m8n8.x4.shared.b16 {%0,%1,%2,%3}, [%4];"
                    : "=r"(af[i][0]), "=r"(af[i][1]), "=r"(af[i][2]), "=r"(af[i][3]) : "r"(ad));
            }
#pragma unroll
            for (int p = 0; p < 2; p++) {
                const uint32_t bd = bBase +
                    SW128((uint32_t)((wn + p * 16 + bRow2) * 128 + kb * 32 + bK2));
                asm volatile("ldmatrix.sync.aligned.m8n8.x4.shared.b16 {%0,%1,%2,%3}, [%4];"
                    : "=r"(bf[p][0]), "=r"(bf[p][1]), "=r"(bf[p][2]), "=r"(bf[p][3]) : "r"(bd));
            }
#pragma unroll
            for (int i = 0; i < 4; i++)
#pragma unroll
                for (int j = 0; j < 4; j++)
                    asm volatile(
                        "mma.sync.aligned.m16n8k16.row.col.f32.f16.f16.f32 "
                        "{%0,%1,%2,%3}, {%4,%5,%6,%7}, {%8,%9}, {%0,%1,%2,%3};"
                        : "+f"(acc[i][j][0]), "+f"(acc[i][j][1]),
                          "+f"(acc[i][j][2]), "+f"(acc[i][j][3])
                        : "r"(af[i][0]), "r"(af[i][1]), "r"(af[i][2]), "r"(af[i][3]),
                          "r"(bf[j >> 1][(j & 1) * 2]), "r"(bf[j >> 1][(j & 1) * 2 + 1]));
        }
    }

#pragma unroll
    for (int i = 0; i < 4; i++)
#pragma unroll
        for (int j = 0; j < 4; j++) {
            const int r = bm + wm + i * 16 + (lane >> 2);
            const int c = bn + wn + j * 8 + (lane & 3) * 2;
            if (sizeof(OutT) == 2) {
                __half2* d0 = (__half2*)((__half*)C + (size_t)r * N + c);
                __half2* d1 = (__half2*)((__half*)C + (size_t)(r + 8) * N + c);
                *d0 = __floats2half2_rn(acc[i][j][0], acc[i][j][1]);
                *d1 = __floats2half2_rn(acc[i][j][2], acc[i][j][3]);
            } else {
                float2 v0; v0.x = acc[i][j][0]; v0.y = acc[i][j][1];
                float2 v1; v1.x = acc[i][j][2]; v1.y = acc[i][j][3];
                *(float2*)((float*)C + (size_t)r * N + c)       = v0;
                *(float2*)((float*)C + (size_t)(r + 8) * N + c) = v1;
            }
        }
}

// =====================================================================
// conversions to fp16
// =====================================================================
__global__ __launch_bounds__(256) void cvt_x(const float* __restrict__ x)
{
    const size_t n = (size_t)ROWS * HID;
    for (size_t i = (size_t)blockIdx.x * 256 + threadIdx.x; i < n; i += (size_t)gridDim.x * 256)
        g_xh[i] = __float2half_rn(x[i]);
}
__global__ __launch_bounds__(256) void cvt_w1(
    const float* __restrict__ Wq, const float* __restrict__ Wb)
{
    const size_t n = (size_t)PD2 * HID;
    for (size_t i = (size_t)blockIdx.x * 256 + threadIdx.x; i < n; i += (size_t)gridDim.x * 256) {
        const int row = (int)(i >> 11);
        const int col = (int)(i & 2047);
        float v;
        if (row < 12288)      v = Wq[i];
        else if (row < 12352) v = Wb[(size_t)(row - 12288) * HID + col];
        else                  v = 0.f;
        g_wh1[i] = __float2half_rn(v);
    }
}
__global__ __launch_bounds__(256) void cvt_wo(const float* __restrict__ Wo)
{
    const size_t n = (size_t)HID * VDIM;
    for (size_t i = (size_t)blockIdx.x * 256 + threadIdx.x; i < n; i += (size_t)gridDim.x * 256)
        g_woh[i] = __float2half_rn(Wo[i]);
}

// =====================================================================
// Sliding-window causal conv (K=4) + SiLU + l2norm split (fp32 input)
// =====================================================================
#define SCHUNK 128

__global__ __launch_bounds__(128) void conv_norm(const float* __restrict__ conv_w)
{
    const int tid = threadIdx.x;
    const int c   = blockIdx.x * 128 + tid;
    const int s0  = blockIdx.y * SCHUNK;
    const int b   = blockIdx.z;
    const bool isqk = (blockIdx.x < 32);

    __shared__ float red[2][4];

    const float w0 = conv_w[c * 4 + 0], w1 = conv_w[c * 4 + 1];
    const float w2 = conv_w[c * 4 + 2], w3 = conv_w[c * 4 + 3];

    const float* src = g_qkvz2 + (size_t)(b * SS) * PD2 + c;

    float xm3 = (s0 >= 3) ? src[(size_t)(s0 - 3) * PD2] : 0.f;
    float xm2 = (s0 >= 2) ? src[(size_t)(s0 - 2) * PD2] : 0.f;
    float xm1 = (s0 >= 1) ? src[(size_t)(s0 - 1) * PD2] : 0.f;
    float cur = src[(size_t)s0 * PD2];

    for (int i = 0; i < SCHUNK; i++) {
        const int s = s0 + i;
        float nxt = 0.f;
        if (i + 1 < SCHUNK) nxt = src[(size_t)(s + 1) * PD2];

        float acc = w3 * cur;
        acc = fmaf(w2, xm1, acc);
        acc = fmaf(w1, xm2, acc);
        acc = fmaf(w0, xm3, acc);
        xm3 = xm2; xm2 = xm1; xm1 = cur; cur = nxt;

        const float val = acc / (1.f + expf(-acc));
        const size_t row = (size_t)b * SS + s;

        if (isqk) {
            float ss = val * val;
#pragma unroll
            for (int off = 16; off; off >>= 1)
                ss += __shfl_xor_sync(0xFFFFFFFFu, ss, off);
            if ((tid & 31) == 0) red[i & 1][tid >> 5] = ss;
            __syncthreads();
            const float tot = red[i & 1][0] + red[i & 1][1] + red[i & 1][2] + red[i & 1][3];
            const float o = val * rsqrtf(tot + 1e-6f);
            if (c < KEYD) g_qn[row * KEYD + c]          = o;
            else          g_kn[row * KEYD + (c - KEYD)] = o;
        } else {
            g_v[row * VDIM + (c - 2 * KEYD)] = val;
        }
    }
}

// =====================================================================
// beta = sigmoid(b); gl = -exp(A_log)*softplus(a+dt_bias)   (LOG decay)
// =====================================================================
__global__ __launch_bounds__(256) void gate_prep(
    const float* __restrict__ dt_bias, const float* __restrict__ A_log)
{
    const int idx = blockIdx.x * 256 + threadIdx.x;
    const int row = idx >> 5, h = idx & 31;
    float bv = g_qkvz2[(size_t)row * PD2 + 12288 + h];
    float av = g_qkvz2[(size_t)row * PD2 + 12320 + h];
    float beta = 1.f / (1.f + expf(-bv));
    float xx = av + dt_bias[h];
    float sp = xx > 20.f ? xx : log1pf(expf(xx));
    g_beta[row * NVH + h] = beta;
    g_gl[row * NVH + h]   = -expf(A_log[h]) * sp;
}

// =====================================================================
// Chunked gated delta-rule scan (WY form) on tensor cores.
// 128 CTAs = (b, h, DV-half), 256 thr, T=64 chunks, state fp32 in smem.
// =====================================================================
#define CK   64
#define NCH  (SS / CK)
#define LKH  136     // halves stride for [64][128]-ish (4 mod 32 words: conflict-free frags)
#define LTH  72      // halves stride for [x][64]
#define LW   65      // fp32 stride
#define LST  129     // fp32 state stride

struct ScanSmem {
    __half k_h [CK * LKH];
    __half q_h [CK * LKH];
    __half sthi[CK * LKH];
    __half stlo[CK * LKH];
    __half kT_h[128 * LTH];
    __half M_h [CK * LTH];
    __half dTo [CK * LTH];
    __half dThi[CK * LTH];
    __half dTlo[CK * LTH];
    float  ST32[CK * LST];     // state transposed: [c][kk]
    float  A32 [CK * LW];
    float  b32 [CK * LW];      // v -> b -> delta (in place)
    float  oacc[CK * LW];
    float  gl_s[CK];
    float  be_s[CK];
    float  cc  [CK];
    float  lam [CK];
    float  Rr  [CK];
};
#define SCAN_SMEM ((int)sizeof(ScanSmem))

__global__ __launch_bounds__(256, 1) void scan_chunk()
{
    extern __shared__ __align__(16) char smraw[];
    ScanSmem* s = (ScanSmem*)smraw;

    const int bx   = blockIdx.x;          // 0..127
    const int b    = bx >> 6;
    const int h    = (bx >> 1) & 31;
    const int half = bx & 1;
    const int kh   = h >> 1;
    const int co   = half * 64;
    const int tid  = threadIdx.x;
    const int warp = tid >> 5, lane = tid & 31;
    const int g    = lane >> 2, q2 = (lane & 3) * 2;
    const int wr0  = (warp & 3) * 16;     // row tile for 64-row outputs
    const int wc0  = (warp >> 2) * 32;    // col group for 64-col outputs

    // zero state
    for (int i = tid; i < CK * LST; i += 256) s->ST32[i] = 0.f;

    for (int nc = 0; nc < NCH; nc++) {
        const int t0 = nc * CK;
        const size_t rb = (size_t)b * SS + t0;

        // ---- phase L: load chunk inputs ----
#pragma unroll
        for (int i = 0; i < 8; i++) {
            const int fid = tid + i * 256;            // 0..2047
            const int row = fid >> 5;
            const int ko  = (fid & 31) * 4;
            float4 kv = *(const float4*)&g_kn[(rb + row) * KEYD + kh * 128 + ko];
            *(__half2*)&s->k_h[row * LKH + ko]     = __floats2half2_rn(kv.x, kv.y);
            *(__half2*)&s->k_h[row * LKH + ko + 2] = __floats2half2_rn(kv.z, kv.w);
            s->kT_h[(ko + 0) * LTH + row] = __float2half_rn(kv.x);
            s->kT_h[(ko + 1) * LTH + row] = __float2half_rn(kv.y);
            s->kT_h[(ko + 2) * LTH + row] = __float2half_rn(kv.z);
            s->kT_h[(ko + 3) * LTH + row] = __float2half_rn(kv.w);
            float4 qv = *(const float4*)&g_qn[(rb + row) * KEYD + kh * 128 + ko];
            *(__half2*)&s->q_h[row * LKH + ko]     = __floats2half2_rn(qv.x, qv.y);
            *(__half2*)&s->q_h[row * LKH + ko + 2] = __floats2half2_rn(qv.z, qv.w);
        }
#pragma unroll
        for (int i = 0; i < 4; i++) {
            const int fid = tid + i * 256;            // 0..1023
            const int row = fid >> 4;
            const int c4  = (fid & 15) * 4;
            float4 vv = *(const float4*)&g_v[(rb + row) * VDIM + h * 128 + co + c4];
            s->b32[row * LW + c4 + 0] = vv.x;
            s->b32[row * LW + c4 + 1] = vv.y;
            s->b32[row * LW + c4 + 2] = vv.z;
            s->b32[row * LW + c4 + 3] = vv.w;
        }
        if (tid < CK)            s->gl_s[tid]      = g_gl[(rb + tid) * NVH + h];
        else if (tid < 2 * CK)   s->be_s[tid - CK] = g_beta[(rb + tid - CK) * NVH + h];
        __syncthreads();

        // ---- decay prefix sums ----
        if (tid < CK) {
            float a = 0.f;
            for (int j = 0; j <= tid; j++) a += s->gl_s[j];
            s->cc[tid] = a;
        }
        __syncthreads();
        if (tid < CK) {
            s->lam[tid] = expf(s->cc[tid]);
            s->Rr[tid]  = expf(s->cc[CK - 1] - s->cc[tid]);
        }
        // ---- state -> split fp16 (transposed layout already) ----
#pragma unroll
        for (int i = 0; i < 32; i++) {
            const int fid = tid + i * 256;            // 0..8191
            const int r  = fid >> 7;
            const int kx = fid & 127;
            float sv = s->ST32[r * LST + kx];
            __half hi = __float2half_rn(sv);
            s->sthi[r * LKH + kx] = hi;
            s->stlo[r * LKH + kx] = __float2half_rn(sv - __half2float(hi));
        }
        __syncthreads();

        // ---- G1: KK->A32, QK->M_h, KS0->b32, QS0->oacc ----
        {
            float acc[4][4];
            // KK
#pragma unroll
            for (int n = 0; n < 4; n++)
#pragma unroll
                for (int i = 0; i < 4; i++) acc[n][i] = 0.f;
            wgemm<4, 8>(s->k_h, LKH, s->k_h, LKH, wr0, wc0, lane, acc);
#pragma unroll
            for (int n = 0; n < 4; n++)
#pragma unroll
                for (int i = 0; i < 4; i++) {
                    const int r  = wr0 + g + (i >= 2 ? 8 : 0);
                    const int cj = wc0 + n * 8 + q2 + (i & 1);
                    s->A32[r * LW + cj] = (cj < r)
                        ? s->be_s[r] * expf(s->cc[r] - s->cc[cj]) * acc[n][i] : 0.f;
                }
            // QK
#pragma unroll
            for (int n = 0; n < 4; n++)
#pragma unroll
                for (int i = 0; i < 4; i++) acc[n][i] = 0.f;
            wgemm<4, 8>(s->q_h, LKH, s->k_h, LKH, wr0, wc0, lane, acc);
#pragma unroll
            for (int n = 0; n < 4; n++)
#pragma unroll
                for (int i = 0; i < 4; i++) {
                    const int r  = wr0 + g + (i >= 2 ? 8 : 0);
                    const int cj = wc0 + n * 8 + q2 + (i & 1);
                    s->M_h[r * LTH + cj] = (cj <= r)
                        ? __float2half_rn(expf(s->cc[r] - s->cc[cj]) * acc[n][i])
                        : __float2half_rn(0.f);
                }
            // KS0 (split state)
#pragma unroll
            for (int n = 0; n < 4; n++)
#pragma unroll
                for (int i = 0; i < 4; i++) acc[n][i] = 0.f;
            wgemm<4, 8>(s->k_h, LKH, s->sthi, LKH, wr0, wc0, lane, acc);
            wgemm<4, 8>(s->k_h, LKH, s->stlo, LKH, wr0, wc0, lane, acc);
#pragma unroll
            for (int n = 0; n < 4; n++)
#pragma unroll
                for (int i = 0; i < 4; i++) {
                    const int r  = wr0 + g + (i >= 2 ? 8 : 0);
                    const int cj = wc0 + n * 8 + q2 + (i & 1);
                    s->b32[r * LW + cj] =
                        s->be_s[r] * (s->b32[r * LW + cj] - s->lam[r] * acc[n][i]);
                }
            // QS0 (split state)
#pragma unroll
            for (int n = 0; n < 4; n++)
#pragma unroll
                for (int i = 0; i < 4; i++) acc[n][i] = 0.f;
            wgemm<4, 8>(s->q_h, LKH, s->sthi, LKH, wr0, wc0, lane, acc);
            wgemm<4, 8>(s->q_h, LKH, s->stlo, LKH, wr0, wc0, lane, acc);
#pragma unroll
            for (int n = 0; n < 4; n++)
#pragma unroll
                for (int i = 0; i < 4; i++) {
                    const int r  = wr0 + g + (i >= 2 ? 8 : 0);
                    const int cj = wc0 + n * 8 + q2 + (i & 1);
                    s->oacc[r * LW + cj] = s->lam[r] * acc[n][i];
                }
        }
        __syncthreads();

        // ---- forward substitution: delta = (I+A)^{-1} b ----
        {
            const int c = tid >> 2;
            const int p = tid & 3;
            for (int t = 0; t < CK; t++) {
                float a = 0.f;
                for (int j = p; j < t; j += 4)
                    a = fmaf(s->A32[t * LW + j], s->b32[j * LW + c], a);
                a += __shfl_xor_sync(0xFFFFFFFFu, a, 1);
                a += __shfl_xor_sync(0xFFFFFFFFu, a, 2);
                const float d = s->b32[t * LW + c] - a;
                if (p == 0)      s->b32[t * LW + c] = d;
                else if (p == 1) s->dTo[c * LTH + t] = __float2half_rn(d);
                else if (p == 2) {
                    const float ru = s->Rr[t] * d;
                    const __half hh = __float2half_rn(ru);
                    s->dThi[c * LTH + t] = hh;
                    s->dTlo[c * LTH + t] = __float2half_rn(ru - __half2float(hh));
                }
                __syncthreads();
            }
        }

        // ---- G2: outputs and state update ----
        {
            // o = oacc + M * delta
            float acc[4][4];
#pragma unroll
            for (int n = 0; n < 4; n++)
#pragma unroll
                for (int i = 0; i < 4; i++) acc[n][i] = 0.f;
            wgemm<4, 4>(s->M_h, LTH, s->dTo, LTH, wr0, wc0, lane, acc);
#pragma unroll
            for (int n = 0; n < 4; n++)
#pragma unroll
                for (int i = 0; i < 4; i++) {
                    const int r  = wr0 + g + (i >= 2 ? 8 : 0);
                    const int cx = wc0 + n * 8 + q2 + (i & 1);
                    g_core[(rb + r) * VDIM + h * 128 + co + cx] =
                        s->oacc[r * LW + cx] + acc[n][i];
                }
            // state: ST32[c][kk] = lam63*ST32 + (R*delta)^T applied via GEMM
            float au[8][4];
#pragma unroll
            for (int n = 0; n < 8; n++)
#pragma unroll
                for (int i = 0; i < 4; i++) au[n][i] = 0.f;
            const int r0u = (warp & 3) * 16;      // c rows
            const int c0u = (warp >> 2) * 64;     // kk cols
            wgemm<8, 4>(s->dThi, LTH, s->kT_h, LTH, r0u, c0u, lane, au);
            wgemm<8, 4>(s->dTlo, LTH, s->kT_h, LTH, r0u, c0u, lane, au);
            const float l63 = s->lam[CK - 1];
#pragma unroll
            for (int n = 0; n < 8; n++)
#pragma unroll
                for (int i = 0; i < 4; i++) {
                    const int r  = r0u + g + (i >= 2 ? 8 : 0);
                    const int kx = c0u + n * 8 + q2 + (i & 1);
                    s->ST32[r * LST + kx] = l63 * s->ST32[r * LST + kx] + au[n][i];
                }
        }
        __syncthreads();
    }
}

// =====================================================================
// RMSNorm(core) * (1+norm_w) * SiLU(z) -> g_gh (fp16)
// =====================================================================
__global__ __launch_bounds__(256) void rms_gate(const float* __restrict__ norm_w)
{
    const int row = blockIdx.x;
    const int tid = threadIdx.x;
    float vals[16];
    float ss = 0.f;
#pragma unroll
    for (int i = 0; i < 16; i++) {
        float v = g_core[(size_t)row * VDIM + i * 256 + tid];
        vals[i] = v;
        ss = fmaf(v, v, ss);
    }
    __shared__ float red[8];
#pragma unroll
    for (int off = 16; off; off >>= 1)
        ss += __shfl_xor_sync(0xFFFFFFFFu, ss, off);
    if ((tid & 31) == 0) red[tid >> 5] = ss;
    __syncthreads();
    float tot = 0.f;
#pragma unroll
    for (int w = 0; w < 8; w++) tot += red[w];
    const float rs = rsqrtf(tot / (float)VDIM + 1e-6f);
#pragma unroll
    for (int i = 0; i < 16; i++) {
        const int c = i * 256 + tid;
        float z  = g_qkvz2[(size_t)row * PD2 + 8192 + c];
        float sz = z / (1.f + expf(-z));
        g_gh[(size_t)row * VDIM + c] =
            __float2half_rn(vals[i] * rs * (1.f + norm_w[c]) * sz);
    }
}

// =====================================================================
extern "C" void kernel_launch(void* const* d_in, const int* in_sizes, int n_in,
                              void* d_out, int out_size)
{
    const float* x       = (const float*)d_in[0];
    const float* W_qkvz  = (const float*)d_in[1];
    const float* W_ba    = (const float*)d_in[2];
    const float* conv_w  = (const float*)d_in[3];
    const float* dt_bias = (const float*)d_in[4];
    const float* A_log   = (const float*)d_in[5];
    const float* norm_w  = (const float*)d_in[6];
    const float* W_out   = (const float*)d_in[7];
    float* out = (float*)d_out;

    float  *p_qkvz2;
    __half *p_xh, *p_wh1, *p_gh, *p_woh;
    cudaGetSymbolAddress((void**)&p_qkvz2, g_qkvz2);
    cudaGetSymbolAddress((void**)&p_xh,    g_xh);
    cudaGetSymbolAddress((void**)&p_wh1,   g_wh1);
    cudaGetSymbolAddress((void**)&p_gh,    g_gh);
    cudaGetSymbolAddress((void**)&p_woh,   g_woh);

    cudaFuncSetAttribute(gemm_f16<float>,  cudaFuncAttributeMaxDynamicSharedMemorySize, GSMEM);
    cudaFuncSetAttribute(scan_chunk,       cudaFuncAttributeMaxDynamicSharedMemorySize, SCAN_SMEM);

    // 0) fp16 conversions
    cvt_x <<<2048, 256>>>(x);
    cvt_w1<<<4096, 256>>>(W_qkvz, W_ba);
    cvt_wo<<<2048, 256>>>(W_out);

    // 1) fused qkvz+ba GEMM -> fp32 buffer
    gemm_f16<float><<<dim3(PD2 / 128, ROWS / 128), 256, GSMEM>>>(p_xh, p_wh1, p_qkvz2, ROWS, PD2, HID);

    // 2) conv + silu + l2norm split
    conv_norm<<<dim3(64, SS / SCHUNK, BB), 128>>>(conv_w);
    // 3) beta / log-decay
    gate_prep<<<ROWS * NVH / 256, 256>>>(dt_bias, A_log);
    // 4) chunked WY delta-rule scan on tensor cores
    scan_chunk<<<128, 256, SCAN_SMEM>>>();
    // 5) RMSNorm + gate -> fp16
    rms_gate<<<ROWS, 256>>>(norm_w);
    // 6) out = gated @ W_out^T  (fp32 out)
    gemm_f16<float><<<dim3(HID / 128, ROWS / 128), 256, GSMEM>>>(p_gh, p_woh, out, ROWS, HID, VDIM);
}